// round 13
// baseline (speedup 1.0000x reference)
#include <cuda_runtime.h>
#include <cuda_fp16.h>
#include <cstdint>
#include <math.h>

#define B_  2
#define H_  2048
#define L_  4096
#define LK  128
#define LAM 0.003f

// Scratch
__device__ __half g_y [(size_t)B_ * H_ * L_];   // gelu(conv) fp16 [B,H,L]
__device__ __half g_wh[(size_t)2 * H_ * H_];    // W fp16 [2H,H]
__device__ __half g_za[(size_t)B_ * H_ * L_];   // a-gate z+bias fp16
__device__ __half g_zg[(size_t)B_ * H_ * L_];   // g-gate z+bias fp16

// ============================================================================
// Helpers
// ============================================================================
__device__ __forceinline__ uint32_t smem_to_u32(const void* p) {
    uint32_t a;
    asm("{ .reg .u64 t; cvta.to.shared.u64 t, %1; cvt.u32.u64 %0, t; }"
        : "=r"(a) : "l"(p));
    return a;
}
__device__ __forceinline__ void cp16(uint32_t dst, const void* src) {
    asm volatile("cp.async.cg.shared.global [%0], [%1], 16;"
                 :: "r"(dst), "l"(src));
}
#define CP_COMMIT() asm volatile("cp.async.commit_group;" ::: "memory")
#define CP_WAIT(N)  asm volatile("cp.async.wait_group %0;" :: "n"(N) : "memory")

#define LDMATRIX_X2(r0, r1, addr) \
    asm volatile("ldmatrix.sync.aligned.m8n8.x2.shared.b16 {%0,%1}, [%2];" \
                 : "=r"(r0), "=r"(r1) : "r"(addr))

#define LDMATRIX_X4(r0, r1, r2, r3, addr) \
    asm volatile("ldmatrix.sync.aligned.m8n8.x4.shared.b16 {%0,%1,%2,%3}, [%4];" \
                 : "=r"(r0), "=r"(r1), "=r"(r2), "=r"(r3) : "r"(addr))

#define LDMATRIX_X4_TRANS(r0, r1, r2, r3, addr) \
    asm volatile("ldmatrix.sync.aligned.m8n8.x4.trans.shared.b16 {%0,%1,%2,%3}, [%4];" \
                 : "=r"(r0), "=r"(r1), "=r"(r2), "=r"(r3) : "r"(addr))

__device__ __forceinline__ void mma_f16(float* c, const uint32_t* a, const uint32_t* b) {
    asm volatile(
        "mma.sync.aligned.m16n8k16.row.col.f32.f16.f16.f32 "
        "{%0,%1,%2,%3}, {%4,%5,%6,%7}, {%8,%9}, {%0,%1,%2,%3};"
        : "+f"(c[0]), "+f"(c[1]), "+f"(c[2]), "+f"(c[3])
        : "r"(a[0]), "r"(a[1]), "r"(a[2]), "r"(a[3]), "r"(b[0]), "r"(b[1]));
}

// ============================================================================
// Kernel 1: fused. Blocks [0,4096): Toeplitz tensor-core FIR conv + fp32 D
// skip + exact GELU -> fp16. Blocks [4096,6144): W -> fp16 conversion.
// ============================================================================
#define NCONV (B_ * H_)
#define NWCVT 2048

__global__ __launch_bounds__(128) void conv_gelu_mma(
    const float* __restrict__ u,
    const float* __restrict__ kern,
    const float* __restrict__ D,
    const float* __restrict__ W)
{
    const int tid = threadIdx.x;

    if (blockIdx.x >= NCONV) {
        size_t base = ((size_t)(blockIdx.x - NCONV) * 4096) + (size_t)tid * 8;
        #pragma unroll
        for (int it = 0; it < 4; it++) {
            size_t i = base + (size_t)it * 1024;
            float4 v0 = *(const float4*)(W + i);
            float4 v1 = *(const float4*)(W + i + 4);
            __half2 hh[4];
            hh[0] = __floats2half2_rn(v0.x, v0.y);
            hh[1] = __floats2half2_rn(v0.z, v0.w);
            hh[2] = __floats2half2_rn(v1.x, v1.y);
            hh[3] = __floats2half2_rn(v1.z, v1.w);
            *(uint4*)(g_wh + i) = *(const uint4*)hh;
        }
        return;
    }

    __shared__ __half uh[4224];
    __shared__ __half At[9][16][24];
    __shared__ float  ks[LK];
    __shared__ float  buf[4][16][10];

    const int bh   = blockIdx.x;
    const int b    = bh / H_;
    const int h    = bh % H_;
    const int wid  = tid >> 5;
    const int lane = tid & 31;

    const float* urow = u   + ((size_t)b * H_ + h) * L_;
    __half*      yrow = g_y + ((size_t)b * H_ + h) * L_;

    {
        float kv = kern[h * LK + tid];
        float a  = fabsf(kv) - LAM;
        a = a > 0.f ? a : 0.f;
        ks[tid] = (kv > 0.f) ? a : ((kv < 0.f) ? -a : 0.f);
    }
    for (int idx = tid; idx < 4224; idx += 128) {
        int l = idx - 128;
        uh[idx] = (l >= 0) ? __float2half_rn(urow[l]) : __float2half_rn(0.f);
    }
    __syncthreads();
    for (int e = tid; e < 9 * 256; e += 128) {
        int s = e >> 8, rr = e & 255, i = rr >> 4, t = rr & 15;
        int d = i - t + 16 * s;
        At[s][i][t] = (d >= 0 && d < LK) ? __float2half_rn(ks[d])
                                         : __float2half_rn(0.f);
    }
    __syncthreads();

    const int r = lane >> 2;
    const int c = lane & 3;
    uint32_t af[9][4];
    #pragma unroll
    for (int s = 0; s < 9; s++) {
        af[s][0] = *(const uint32_t*)&At[s][r][2 * c];
        af[s][1] = *(const uint32_t*)&At[s][r + 8][2 * c];
        af[s][2] = *(const uint32_t*)&At[s][r][2 * c + 8];
        af[s][3] = *(const uint32_t*)&At[s][r + 8][2 * c + 8];
    }

    const uint32_t uh_u32 = smem_to_u32(uh);
    const int lm = (lane < 8) ? 16 * lane
                 : (lane < 16 ? 16 * (lane - 8) + 8 : 0);

    const float Dh = D[h];
    float (*bw)[10] = buf[wid];

    #pragma unroll 1
    for (int nt = 0; nt < 8; nt++) {
        const int n0 = wid * 64 + nt * 8;
        float cc[4] = {0.f, 0.f, 0.f, 0.f};

        #pragma unroll
        for (int s = 0; s < 9; s++) {
            const int base = 128 + 16 * (n0 - s);
            uint32_t bb[2];
            LDMATRIX_X2(bb[0], bb[1], uh_u32 + (uint32_t)(base + lm) * 2u);
            mma_f16(cc, af[s], bb);
        }

        bw[r][2 * c]         = cc[0];
        bw[r][2 * c + 1]     = cc[1];
        bw[r + 8][2 * c]     = cc[2];
        bw[r + 8][2 * c + 1] = cc[3];
        __syncwarp();

        const int lbase = 16 * n0 + 4 * lane;
        float4 uv = *(const float4*)&urow[lbase];
        const float us4[4] = {uv.x, uv.y, uv.z, uv.w};
        __half hv[4];
        #pragma unroll
        for (int j = 0; j < 4; j++) {
            int li = 4 * lane + j;
            float x = bw[li & 15][li >> 4] + Dh * us4[j];
            float gv = 0.5f * x * (1.f + erff(x * 0.70710678118654752f));
            hv[j] = __float2half_rn(gv);
        }
        *(uint2*)&yrow[lbase] = *(const uint2*)hv;
        __syncwarp();
    }
}

// ============================================================================
// Kernel 2: single-gate fp16 GEMM, CTA 128(h) x 64(l), 256 thr (8 warps,
// 4Mx2N, warp tile 32x32, 32 accs -> ~60 regs). __launch_bounds__(256,3)
// => 3 CTAs/SM = 6 warps/SMSP (pipe-feeding experiment).
// grid (L/64, H/128, 2*B); z: b = z>>1, gate = z&1. Output: z+bias fp16.
// BK=32, 3-stage cp.async pipeline, one barrier per chunk.
// ============================================================================
#define BK       32
#define NKC      (H_ / BK)          // 64
#define A_STRH   40
#define B_STRH   72
#define OFF_B    (128 * A_STRH)                      // 5120 halves
#define STAGE_H  (128 * A_STRH + BK * B_STRH)        // 7424 halves = 14848 B
#define NSTG     3
#define SMEM_BYTES (NSTG * STAGE_H * 2)              // 44544 B

__global__ __launch_bounds__(256, 3) void gemm_z_tc(
    const float* __restrict__ bias)
{
    extern __shared__ __half smem_h[];
    const uint32_t smem_u = smem_to_u32(smem_h);

    const int tid  = threadIdx.x;
    const int wid  = tid >> 5;
    const int lane = tid & 31;
    const int l0   = blockIdx.x * 64;
    const int h0   = blockIdx.y * 128;
    const int b    = blockIdx.z >> 1;
    const int gate = blockIdx.z & 1;

    const __half* Y  = g_y  + (size_t)b * H_ * L_;
    const __half* Wg = g_wh + (size_t)gate * H_ * H_;
    __half*       Z  = (gate ? g_zg : g_za) + (size_t)b * H_ * L_;

    // cp.async coordinates
    const int ar = tid >> 1;             // 0..127  A row
    const int ac = (tid & 1) * 16;       // 0 or 16 (then +0/+8)
    const int br = tid >> 3;             // 0..31   B row (k)
    const int bc = (tid & 7) * 8;        // 0..56   B col (n)

    const __half* pW = &Wg[(size_t)(h0 + ar) * H_ + ac];
    const __half* pY = &Y[(size_t)br * L_ + l0 + bc];

    auto issue = [&](int k0, int s) {
        uint32_t sb = smem_u + (uint32_t)(s * STAGE_H) * 2u;
        cp16(sb + (uint32_t)(ar * A_STRH + ac) * 2u,     pW + k0);
        cp16(sb + (uint32_t)(ar * A_STRH + ac + 8) * 2u, pW + k0 + 8);
        cp16(sb + (uint32_t)(OFF_B + br * B_STRH + bc) * 2u,
             pY + (size_t)k0 * L_);
    };

    float acc[2][4][4];
    #pragma unroll
    for (int mt = 0; mt < 2; mt++)
        #pragma unroll
        for (int nt = 0; nt < 4; nt++)
            #pragma unroll
            for (int q = 0; q < 4; q++) acc[mt][nt][q] = 0.f;

    const int wm = (wid & 3) * 32;       // M offset within 128
    const int wn = (wid >> 2) * 32;      // N offset within 64
    const int g8 = lane >> 2;
    const int t4 = lane & 3;

    const int lm_k = (lane & 7) | (((lane >> 3) & 1) << 3);
    const int lm_n = (lane >> 4) << 3;
    const uint32_t b_lane_off =
        (uint32_t)(OFF_B + lm_k * B_STRH + wn + lm_n) * 2u;

    const uint32_t a_lane_base =
        (uint32_t)((wm + (lane & 15)) * A_STRH + ((lane >> 4) << 3)) * 2u;

    issue(0,  0);  CP_COMMIT();
    issue(BK, 1);  CP_COMMIT();

    for (int kc = 0; kc < NKC; kc++) {
        if (kc < NKC - 1) { CP_WAIT(1); } else { CP_WAIT(0); }
        __syncthreads();

        if (kc + 2 < NKC) {
            issue((kc + 2) * BK, (kc + 2) % NSTG);   // overwrites stage (kc-1)%3
            CP_COMMIT();
        }

        const uint32_t stg_u = smem_u + (uint32_t)((kc % NSTG) * STAGE_H) * 2u;

        #pragma unroll
        for (int ks = 0; ks < 2; ks++) {
            const int kb = ks * 16;

            uint32_t bb[4][2];
            LDMATRIX_X4_TRANS(bb[0][0], bb[0][1], bb[1][0], bb[1][1],
                              stg_u + b_lane_off + (uint32_t)(kb * B_STRH) * 2u);
            LDMATRIX_X4_TRANS(bb[2][0], bb[2][1], bb[3][0], bb[3][1],
                              stg_u + b_lane_off + (uint32_t)(kb * B_STRH + 16) * 2u);

            #pragma unroll
            for (int mt = 0; mt < 2; mt++) {
                uint32_t af[4];
                LDMATRIX_X4(af[0], af[1], af[2], af[3],
                            stg_u + a_lane_base + (uint32_t)(mt * 16 * A_STRH + kb) * 2u);
                #pragma unroll
                for (int nt = 0; nt < 4; nt++)
                    mma_f16(acc[mt][nt], af, bb[nt]);
            }
        }
    }

    // ---- epilogue: add bias, store fp16 z ----
    #pragma unroll
    for (int mt = 0; mt < 2; mt++) {
        const int h_lo = h0 + wm + mt * 16 + g8;
        const int h_hi = h_lo + 8;
        const float b0 = bias[gate * H_ + h_lo];
        const float b1 = bias[gate * H_ + h_hi];
        #pragma unroll
        for (int nt = 0; nt < 4; nt++) {
            const int l = l0 + wn + nt * 8 + 2 * t4;
            __half2 z2;
            z2 = __floats2half2_rn(acc[mt][nt][0] + b0, acc[mt][nt][1] + b0);
            *(__half2*)&Z[(size_t)h_lo * L_ + l] = z2;
            z2 = __floats2half2_rn(acc[mt][nt][2] + b1, acc[mt][nt][3] + b1);
            *(__half2*)&Z[(size_t)h_hi * L_ + l] = z2;
        }
    }
}

// ============================================================================
// Kernel 3: GLU  out = za * sigmoid(zg)
// ============================================================================
__global__ __launch_bounds__(256) void glu_kernel(float* __restrict__ out)
{
    size_t i = ((size_t)blockIdx.x * 256 + threadIdx.x) * 8;
    uint4 pa = *(const uint4*)(g_za + i);
    uint4 pg = *(const uint4*)(g_zg + i);
    const __half2* ha = (const __half2*)&pa;
    const __half2* hg = (const __half2*)&pg;
    float4 o[2];
    float* op = (float*)o;
    #pragma unroll
    for (int j = 0; j < 4; j++) {
        float2 a2 = __half22float2(ha[j]);
        float2 g2 = __half22float2(hg[j]);
        op[2*j]   = __fdividef(a2.x, 1.f + __expf(-g2.x));
        op[2*j+1] = __fdividef(a2.y, 1.f + __expf(-g2.y));
    }
    *(float4*)(out + i)     = o[0];
    *(float4*)(out + i + 4) = o[1];
}

// ============================================================================
extern "C" void kernel_launch(void* const* d_in, const int* in_sizes, int n_in,
                              void* d_out, int out_size)
{
    const float* u    = (const float*)d_in[0];   // [B,H,L]
    const float* kern = (const float*)d_in[1];   // [1,H,128]
    const float* D    = (const float*)d_in[2];   // [1,H]
    const float* W    = (const float*)d_in[3];   // [2H,H]
    const float* bias = (const float*)d_in[4];   // [2H]
    float* out = (float*)d_out;                  // [B,H,L]

    conv_gelu_mma<<<NCONV + NWCVT, 128>>>(u, kern, D, W);

    cudaFuncSetAttribute(gemm_z_tc,
                         cudaFuncAttributeMaxDynamicSharedMemorySize, SMEM_BYTES);
    dim3 grid(L_ / 64, H_ / 128, 2 * B_);
    gemm_z_tc<<<grid, 256, SMEM_BYTES>>>(bias);

    glu_kernel<<<(int)(((size_t)B_ * H_ * L_) / (256 * 8)), 256>>>(out);
}